// round 9
// baseline (speedup 1.0000x reference)
#include <cuda_runtime.h>
#include <cuda_fp16.h>

#define NN 100000
#define EE 3200000
#define GG 2048
#define HH 64
#define SCAN_BS 512

// Scratch (device globals — no allocation allowed).
__device__ uint4   d_uh[(NN + 1) * 8];   // (h @ W) * dinv, fp16; row NN = dummy zeros (never written)
__device__ uint4   d_hh[NN * 8];         // node features h, fp16
__device__ __half  d_wh[3 * HH * HH];    // conv weights, fp16 (converted per call)
__device__ float   d_dinv[NN];           // rsqrt(deg+1)
__device__ int     d_degi[NN];           // in-degree (re-zeroed at end of call by k_poolmlp)
__device__ int     d_off[NN];            // padded CSR offsets
__device__ unsigned short d_epos[EE];    // per-edge rank within its target
__device__ int     d_csr[EE + 7 * NN];   // grouped sources, padded to x8 per node
__device__ volatile unsigned long long d_bstate[256];  // lookback scan state

__device__ __forceinline__ unsigned smem_u32(const void* p) {
    return (unsigned)__cvta_generic_to_shared(p);
}
__device__ __forceinline__ void cp16(void* dst, const void* src) {
    asm volatile("cp.async.ca.shared.global [%0], [%1], 16;"
                 :: "r"(smem_u32(dst)), "l"(src));
}
__device__ __forceinline__ void cp_wait_all() {
    asm volatile("cp.async.commit_group;");
    asm volatile("cp.async.wait_group 0;");
}

// packed-f32x2 helpers (B300 native)
__device__ __forceinline__ unsigned long long pack_h2_to_f32x2(unsigned h) {
    float2 f = __half22float2(*(__half2*)&h);
    unsigned long long r;
    asm("mov.b64 %0, {%1, %2};" : "=l"(r) : "f"(f.x), "f"(f.y));
    return r;
}
// acc += float2( hadd2(ha, hb) )   — one HADD2, two cvt, one add.f32x2
__device__ __forceinline__ void acc_pair(unsigned long long& acc, unsigned ha, unsigned hb) {
    __half2 s = __hadd2(*(__half2*)&ha, *(__half2*)&hb);
    float2 f = __half22float2(s);
    unsigned long long t;
    asm("mov.b64 %0, {%1, %2};" : "=l"(t) : "f"(f.x), "f"(f.y));
    asm("add.rn.f32x2 %0, %0, %1;" : "+l"(acc) : "l"(t));
}
__device__ __forceinline__ float2 unpack_f32x2(unsigned long long a) {
    float2 f;
    asm("mov.b64 {%0, %1}, %2;" : "=f"(f.x), "=f"(f.y) : "l"(a));
    return f;
}

// ---------------------------------------------------------------- deg (+ scan-state zero + W->fp16)
__global__ void k_deg(const int* __restrict__ col, const float* __restrict__ conv_w,
                      int e_cnt, int deg_blocks) {
    int bid = blockIdx.x;
    if (bid >= deg_blocks) {  // W conversion blocks
        int idx = (bid - deg_blocks) * 256 + threadIdx.x;
        if (idx < 3 * HH * HH / 2) {
            float2 wv = ((const float2*)conv_w)[idx];
            ((__half2*)d_wh)[idx] = __float22half2_rn(wv);
        }
        return;
    }
    int e = bid * blockDim.x + threadIdx.x;
    if (e < 256) d_bstate[e] = 0ULL;
    if (e >= e_cnt) return;
    d_epos[e] = (unsigned short)atomicAdd(&d_degi[col[e]], 1);
}

// ---------------------------------------------------------------- single-pass scan (+ pad write)
__device__ __forceinline__ int warp_iscan(int v) {
    int lane = threadIdx.x & 31;
#pragma unroll
    for (int o = 1; o < 32; o <<= 1) {
        int t = __shfl_up_sync(0xFFFFFFFFu, v, o);
        if (lane >= o) v += t;
    }
    return v;
}

__global__ void __launch_bounds__(SCAN_BS) k_scan(int n) {
    __shared__ int ws[16];
    __shared__ int s_prefix;
    int t = threadIdx.x, bid = blockIdx.x;
    int lane = t & 31, wid = t >> 5;
    int i = bid * SCAN_BS + t;

    int deg = (i < n) ? d_degi[i] : 0;
    int pdeg = (deg + 7) & ~7;

    int s = warp_iscan(pdeg);
    if (lane == 31) ws[wid] = s;
    __syncthreads();
    if (wid == 0) {
        int wv = (lane < 16) ? ws[lane] : 0;
        int wsum = warp_iscan(wv);
        if (lane < 16) ws[lane] = wsum;
    }
    __syncthreads();
    int base = (wid > 0) ? ws[wid - 1] : 0;
    int incl = base + s;
    int total = ws[15];

    if (wid == 0) {
        if (bid == 0) {
            if (lane == 0) {
                s_prefix = 0;
                d_bstate[0] = (2ULL << 32) | (unsigned)total;
            }
        } else {
            if (lane == 0)
                d_bstate[bid] = (1ULL << 32) | (unsigned)total;
            long long run = 0;
            int wbase = bid;
            while (true) {
                int b = wbase - 32 + lane;
                unsigned long long st;
                if (b >= 0) {
                    do { st = d_bstate[b]; } while ((st >> 32) == 0);
                } else {
                    st = (2ULL << 32);
                }
                unsigned pm = __ballot_sync(0xFFFFFFFFu, (st >> 32) == 2u);
                if (pm) {
                    int lead = 31 - __clz(pm);
                    long long v = (lane >= lead) ? (long long)(unsigned)st : 0;
#pragma unroll
                    for (int o = 16; o > 0; o >>= 1) v += __shfl_xor_sync(0xFFFFFFFFu, v, o);
                    run += v;
                    break;
                } else {
                    long long v = (long long)(unsigned)st;
#pragma unroll
                    for (int o = 16; o > 0; o >>= 1) v += __shfl_xor_sync(0xFFFFFFFFu, v, o);
                    run += v;
                    wbase -= 32;
                }
            }
            if (lane == 0) {
                s_prefix = (int)run;
                d_bstate[bid] = (2ULL << 32) | (unsigned)(run + total);
            }
        }
    }
    __syncthreads();

    if (i < n) {
        int off = s_prefix + incl - pdeg;
        d_off[i] = off;
        d_dinv[i] = rsqrtf((float)deg + 1.0f);
        for (int k = deg; k < pdeg; k++) d_csr[off + k] = NN;  // pads -> zero row
    }
}

// CSR fill: plain store via precomputed rank (no atomics, no smem, full occupancy)
__global__ void k_fill(const int* __restrict__ rowi, const int* __restrict__ coli, int e_cnt) {
    int e = blockIdx.x * blockDim.x + threadIdx.x;
    if (e >= e_cnt) return;
    d_csr[__ldg(&d_off[coli[e]]) + (int)d_epos[e]] = rowi[e];
}

// ---------------------------------------------------------------- GEMM (tensor core)
// u = (h @ W) * dinv -> fp16. Block: 128 rows x 64 cols, 8 warps, cp.async fills.
__global__ void __launch_bounds__(256) k_gemm(int layer,
                                              const int* __restrict__ x,
                                              const float* __restrict__ emb,
                                              int n) {
    __shared__ __half sA[128 * 72];   // h rows fp16; reused for D staging
    __shared__ __half sB[64 * 72];    // W [k][n] fp16

    int tid = threadIdx.x;
    int row0 = blockIdx.x * 128;
    const __half* Wh = d_wh + layer * HH * HH;

#pragma unroll
    for (int i = 0; i < 2; i++) {
        int idx = tid + 256 * i;          // 512 slots: 64 rows x 8 col-chunks
        int k = idx >> 3, c8 = idx & 7;
        cp16(&sB[k * 72 + c8 * 8], &Wh[k * 64 + c8 * 8]);
    }

    if (layer == 0) {
        const float4* emb4 = (const float4*)emb;
#pragma unroll
        for (int i = 0; i < 8; i++) {
            int idx = tid + 256 * i;
            int r = idx >> 4, c4 = idx & 15;
            int grow = row0 + r;
            float4 v = make_float4(0.f, 0.f, 0.f, 0.f);
            if (grow < n) {
                int vx = __ldg(&x[grow]);
                v = __ldg(&emb4[vx * 16 + c4]);
            }
            __half2* dst = (__half2*)&sA[r * 72 + c4 * 4];
            dst[0] = __float22half2_rn(make_float2(v.x, v.y));
            dst[1] = __float22half2_rn(make_float2(v.z, v.w));
        }
    } else {
#pragma unroll
        for (int i = 0; i < 4; i++) {
            int idx = tid + 256 * i;
            int r = idx >> 3, c8 = idx & 7;
            int grow = row0 + r;
            if (grow < n) cp16(&sA[r * 72 + c8 * 8], &d_hh[grow * 8 + c8]);
            else          *(uint4*)&sA[r * 72 + c8 * 8] = make_uint4(0, 0, 0, 0);
        }
    }
    cp_wait_all();
    __syncthreads();

    int w = tid >> 5, lane = tid & 31;
    int m0 = w * 16;
    int sub = lane >> 3, lrow = lane & 7;
    int bl = lane & 15;

    unsigned af[4][4];
#pragma unroll
    for (int kk = 0; kk < 4; kk++) {
        unsigned aaddr = smem_u32(&sA[(m0 + (sub & 1) * 8 + lrow) * 72 + kk * 16 + (sub >> 1) * 8]);
        asm volatile("ldmatrix.sync.aligned.m8n8.x4.shared.b16 {%0,%1,%2,%3}, [%4];"
                     : "=r"(af[kk][0]), "=r"(af[kk][1]), "=r"(af[kk][2]), "=r"(af[kk][3])
                     : "r"(aaddr));
    }

    float acc[8][4];
#pragma unroll
    for (int j = 0; j < 8; j++) {
        acc[j][0] = 0.f; acc[j][1] = 0.f; acc[j][2] = 0.f; acc[j][3] = 0.f;
    }

#pragma unroll
    for (int kk = 0; kk < 4; kk++) {
#pragma unroll
        for (int j = 0; j < 8; j++) {
            unsigned baddr = smem_u32(&sB[(kk * 16 + (bl >> 3) * 8 + (bl & 7)) * 72 + j * 8]);
            unsigned b0, b1;
            asm volatile("ldmatrix.sync.aligned.m8n8.x2.trans.shared.b16 {%0,%1}, [%2];"
                         : "=r"(b0), "=r"(b1) : "r"(baddr));
            asm volatile("mma.sync.aligned.m16n8k16.row.col.f32.f16.f16.f32 "
                         "{%0,%1,%2,%3},{%4,%5,%6,%7},{%8,%9},{%0,%1,%2,%3};"
                         : "+f"(acc[j][0]), "+f"(acc[j][1]), "+f"(acc[j][2]), "+f"(acc[j][3])
                         : "r"(af[kk][0]), "r"(af[kk][1]), "r"(af[kk][2]), "r"(af[kk][3]),
                           "r"(b0), "r"(b1));
        }
    }
    __syncthreads();   // done reading sA -> reuse for D staging

    int rloc = m0 + (lane >> 2);
    int rA = row0 + rloc, rB = rA + 8;
    float dvA = (rA < n) ? __ldg(&d_dinv[rA]) : 0.f;
    float dvB = (rB < n) ? __ldg(&d_dinv[rB]) : 0.f;
    __half2* sA2 = (__half2*)sA;   // 36 half2 per row
    int ch = lane & 3;
#pragma unroll
    for (int j = 0; j < 8; j++) {
        int c2 = j * 4 + ch;
        sA2[rloc * 36 + c2]       = __float22half2_rn(make_float2(acc[j][0] * dvA, acc[j][1] * dvA));
        sA2[(rloc + 8) * 36 + c2] = __float22half2_rn(make_float2(acc[j][2] * dvB, acc[j][3] * dvB));
    }
    __syncthreads();

#pragma unroll
    for (int i = 0; i < 4; i++) {
        int idx = tid + 256 * i;
        int r = idx >> 3, c8 = idx & 7;
        int grow = row0 + r;
        if (grow < n) d_uh[grow * 8 + c8] = *(uint4*)&sA[r * 72 + c8 * 8];
    }
}

// ---------------------------------------------------------------- gather + epilogue
// 8 threads/node. Pairwise fp16 pre-add (HADD2) + packed f32x2 accumulation.
__global__ void __launch_bounds__(256) k_gather(const float* __restrict__ b, int layer, int n) {
    int idx = blockIdx.x * blockDim.x + threadIdx.x;
    int nd = idx >> 3;
    if (nd >= n) return;
    int p = idx & 7;
    int lane = threadIdx.x & 31;
    unsigned grpmask = 0xFFu << (lane & ~7);

    int beg = __ldg(&d_off[nd]);
    int deg = __ldg(&d_degi[nd]);

    // init accumulators from self-loop term
    uint4 vs = d_uh[nd * 8 + p];
    unsigned long long a01 = pack_h2_to_f32x2(vs.x);
    unsigned long long a23 = pack_h2_to_f32x2(vs.y);
    unsigned long long a45 = pack_h2_to_f32x2(vs.z);
    unsigned long long a67 = pack_h2_to_f32x2(vs.w);

    for (int k = 0; k < deg; k += 8) {
        int si = __ldg(&d_csr[beg + k + p]);   // pads point at zero row NN
#pragma unroll
        for (int j = 0; j < 8; j += 2) {
            int s0 = __shfl_sync(grpmask, si, j, 8);
            int s1 = __shfl_sync(grpmask, si, j + 1, 8);
            uint4 va = __ldg(&d_uh[s0 * 8 + p]);
            uint4 vb = __ldg(&d_uh[s1 * 8 + p]);
            acc_pair(a01, va.x, vb.x);
            acc_pair(a23, va.y, vb.y);
            acc_pair(a45, va.z, vb.z);
            acc_pair(a67, va.w, vb.w);
        }
    }

    float2 f01 = unpack_f32x2(a01);
    float2 f23 = unpack_f32x2(a23);
    float2 f45 = unpack_f32x2(a45);
    float2 f67 = unpack_f32x2(a67);

    float dv = __ldg(&d_dinv[nd]);
    const float4* b4 = (const float4*)b;
    float4 bb0 = __ldg(&b4[p * 2 + 0]);
    float4 bb1 = __ldg(&b4[p * 2 + 1]);

    float v0 = fmaxf(fmaf(dv, f01.x, bb0.x), 0.f);
    float v1 = fmaxf(fmaf(dv, f01.y, bb0.y), 0.f);
    float v2 = fmaxf(fmaf(dv, f23.x, bb0.z), 0.f);
    float v3 = fmaxf(fmaf(dv, f23.y, bb0.w), 0.f);
    float v4 = fmaxf(fmaf(dv, f45.x, bb1.x), 0.f);
    float v5 = fmaxf(fmaf(dv, f45.y, bb1.y), 0.f);
    float v6 = fmaxf(fmaf(dv, f67.x, bb1.z), 0.f);
    float v7 = fmaxf(fmaf(dv, f67.y, bb1.w), 0.f);

    if (layer != 0) {
        uint4 hv = d_hh[nd * 8 + p];
        float2 f;
        f = __half22float2(*(__half2*)&hv.x); v0 += f.x; v1 += f.y;
        f = __half22float2(*(__half2*)&hv.y); v2 += f.x; v3 += f.y;
        f = __half22float2(*(__half2*)&hv.z); v4 += f.x; v5 += f.y;
        f = __half22float2(*(__half2*)&hv.w); v6 += f.x; v7 += f.y;
    }

    uint4 o;
    __half2 t0, t1;
    t0 = __float22half2_rn(make_float2(v0, v1));
    t1 = __float22half2_rn(make_float2(v2, v3));
    o.x = *(unsigned*)&t0; o.y = *(unsigned*)&t1;
    t0 = __float22half2_rn(make_float2(v4, v5));
    t1 = __float22half2_rn(make_float2(v6, v7));
    o.z = *(unsigned*)&t0; o.w = *(unsigned*)&t1;
    d_hh[nd * 8 + p] = o;
}

// ---------------------------------------------------------------- fused pool + MLP (+ state cleanup)
__global__ void __launch_bounds__(256) k_poolmlp(const int* __restrict__ batch,
                                                 const float* __restrict__ w1, const float* __restrict__ b1,
                                                 const float* __restrict__ w2, const float* __restrict__ b2,
                                                 const float* __restrict__ w3, const float* __restrict__ b3,
                                                 float* __restrict__ out, int n) {
    __shared__ float sg[8][64];
    __shared__ float sa[8][32];

    int gt = blockIdx.x * blockDim.x + threadIdx.x;
    for (int i = gt; i < n; i += gridDim.x * blockDim.x) d_degi[i] = 0;

    int wlocal = threadIdx.x >> 5;
    int g = gt >> 5;
    int lane = threadIdx.x & 31;
    if (g >= GG) return;

    int lo = 0, hi = n;
    while (lo < hi) { int m = (lo + hi) >> 1; if (__ldg(&batch[m]) < g) lo = m + 1; else hi = m; }
    int lo2 = lo, hi2 = n;
    while (lo2 < hi2) { int m = (lo2 + hi2) >> 1; if (__ldg(&batch[m]) < g + 1) lo2 = m + 1; else hi2 = m; }
    int cnt = lo2 - lo;

    const unsigned* h2 = (const unsigned*)d_hh;
    float s0 = 0.f, s1 = 0.f;
    for (int i = lo; i < lo2; i++) {
        unsigned hv = __ldg(&h2[i * 32 + lane]);
        float2 f = __half22float2(*(__half2*)&hv);
        s0 += f.x; s1 += f.y;
    }
    float inv = 1.0f / fmaxf((float)cnt, 1.0f);
    sg[wlocal][lane * 2 + 0] = s0 * inv;
    sg[wlocal][lane * 2 + 1] = s1 * inv;
    __syncwarp();

    float acc1 = __ldg(&b1[lane]);
#pragma unroll 16
    for (int k = 0; k < 64; k++)
        acc1 = fmaf(sg[wlocal][k], __ldg(&w1[k * 32 + lane]), acc1);
    acc1 = fmaxf(acc1, 0.f);
    sa[wlocal][lane] = acc1;
    __syncwarp();

    float acc2 = 0.f;
    if (lane < 16) {
        acc2 = __ldg(&b2[lane]);
#pragma unroll
        for (int k = 0; k < 32; k++)
            acc2 = fmaf(sa[wlocal][k], __ldg(&w2[k * 16 + lane]), acc2);
        acc2 = fmaxf(acc2, 0.f);
        acc2 *= __ldg(&w3[lane]);
    }
#pragma unroll
    for (int o = 16; o > 0; o >>= 1) acc2 += __shfl_xor_sync(0xFFFFFFFFu, acc2, o);
    if (lane == 0) out[g] = acc2 + __ldg(&b3[0]);
}

// ---------------------------------------------------------------- launch
extern "C" void kernel_launch(void* const* d_in, const int* in_sizes, int n_in,
                              void* d_out, int out_size) {
    const int*   x      = (const int*)d_in[0];
    const int*   ei     = (const int*)d_in[1];
    const int*   batch  = (const int*)d_in[2];
    const float* emb    = (const float*)d_in[3];
    const float* conv_w = (const float*)d_in[4];
    const float* conv_b = (const float*)d_in[5];
    const float* w1     = (const float*)d_in[6];
    const float* b1     = (const float*)d_in[7];
    const float* w2     = (const float*)d_in[8];
    const float* b2     = (const float*)d_in[9];
    const float* w3     = (const float*)d_in[10];
    const float* b3     = (const float*)d_in[11];
    float* out = (float*)d_out;

    int n = in_sizes[0];       // 100000
    int e = in_sizes[1] / 2;   // 3200000
    const int* row = ei;       // source
    const int* col = ei + e;   // target

    int tb = 256;
    int g_n8 = (n * 8 + tb - 1) / tb;
    int g_e  = (e + tb - 1) / tb;
    int g_rows = (n + 127) / 128;
    int nb_scan = (n + SCAN_BS - 1) / SCAN_BS;
    int wcvt_blocks = (3 * HH * HH / 2 + tb - 1) / tb;   // 24

    k_deg<<<g_e + wcvt_blocks, tb>>>(col, conv_w, e, g_e);
    k_scan<<<nb_scan, SCAN_BS>>>(n);
    k_fill<<<g_e, tb>>>(row, col, e);
    k_gemm<<<g_rows, tb>>>(0, x, emb, n);
    k_gather<<<g_n8, tb>>>(conv_b, 0, n);
    for (int l = 1; l < 3; l++) {
        k_gemm<<<g_rows, tb>>>(l, x, emb, n);
        k_gather<<<g_n8, tb>>>(conv_b + l * HH, l, n);
    }
    k_poolmlp<<<(GG * 32 + tb - 1) / tb, tb>>>(batch, w1, b1, w2, b2, w3, b3, out, n);
}

// round 10
// speedup vs baseline: 1.0206x; 1.0206x over previous
#include <cuda_runtime.h>
#include <cuda_fp16.h>

#define NN 100000
#define EE 3200000
#define GG 2048
#define HH 64
#define SCAN_BS 512

// Scratch (device globals — no allocation allowed).
__device__ uint4   d_uh[(NN + 1) * 8];   // (h @ W) * dinv, fp16; row NN = dummy zeros (never written)
__device__ uint4   d_hh[NN * 8];         // node features h, fp16
__device__ __half  d_wh[3 * HH * HH];    // conv weights, fp16 (converted per call)
__device__ float   d_dinv[NN];           // rsqrt(deg+1)
__device__ int     d_degi[NN];           // in-degree (re-zeroed at end of call by k_poolmlp)
__device__ int     d_off[NN];            // padded CSR offsets
__device__ unsigned char d_epos[EE];     // per-edge rank within its target (deg << 256)
__device__ int     d_csr[EE + 7 * NN];   // grouped sources, padded to x8 per node
__device__ volatile unsigned long long d_bstate[256];  // lookback scan state

__device__ __forceinline__ unsigned smem_u32(const void* p) {
    return (unsigned)__cvta_generic_to_shared(p);
}
__device__ __forceinline__ void cp16(void* dst, const void* src) {
    asm volatile("cp.async.ca.shared.global [%0], [%1], 16;"
                 :: "r"(smem_u32(dst)), "l"(src));
}
__device__ __forceinline__ void cp_wait_all() {
    asm volatile("cp.async.commit_group;");
    asm volatile("cp.async.wait_group 0;");
}

// ---------------------------------------------------------------- deg (+ scan-state zero + W->fp16)
__global__ void k_deg(const int* __restrict__ col, const float* __restrict__ conv_w,
                      int e_cnt, int deg_blocks) {
    int bid = blockIdx.x;
    if (bid >= deg_blocks) {  // W conversion blocks
        int idx = (bid - deg_blocks) * 256 + threadIdx.x;
        if (idx < 3 * HH * HH / 2) {
            float2 wv = ((const float2*)conv_w)[idx];
            ((__half2*)d_wh)[idx] = __float22half2_rn(wv);
        }
        return;
    }
    int e = bid * blockDim.x + threadIdx.x;
    if (e < 256) d_bstate[e] = 0ULL;
    if (e >= e_cnt) return;
    d_epos[e] = (unsigned char)atomicAdd(&d_degi[col[e]], 1);
}

// ---------------------------------------------------------------- single-pass scan (+ pad write)
__device__ __forceinline__ int warp_iscan(int v) {
    int lane = threadIdx.x & 31;
#pragma unroll
    for (int o = 1; o < 32; o <<= 1) {
        int t = __shfl_up_sync(0xFFFFFFFFu, v, o);
        if (lane >= o) v += t;
    }
    return v;
}

__global__ void __launch_bounds__(SCAN_BS) k_scan(int n) {
    __shared__ int ws[16];
    __shared__ int s_prefix;
    int t = threadIdx.x, bid = blockIdx.x;
    int lane = t & 31, wid = t >> 5;
    int i = bid * SCAN_BS + t;

    int deg = (i < n) ? d_degi[i] : 0;
    int pdeg = (deg + 7) & ~7;

    int s = warp_iscan(pdeg);
    if (lane == 31) ws[wid] = s;
    __syncthreads();
    if (wid == 0) {
        int wv = (lane < 16) ? ws[lane] : 0;
        int wsum = warp_iscan(wv);
        if (lane < 16) ws[lane] = wsum;
    }
    __syncthreads();
    int base = (wid > 0) ? ws[wid - 1] : 0;
    int incl = base + s;
    int total = ws[15];

    if (wid == 0) {
        if (bid == 0) {
            if (lane == 0) {
                s_prefix = 0;
                d_bstate[0] = (2ULL << 32) | (unsigned)total;
            }
        } else {
            if (lane == 0)
                d_bstate[bid] = (1ULL << 32) | (unsigned)total;
            long long run = 0;
            int wbase = bid;
            while (true) {
                int b = wbase - 32 + lane;
                unsigned long long st;
                if (b >= 0) {
                    do { st = d_bstate[b]; } while ((st >> 32) == 0);
                } else {
                    st = (2ULL << 32);
                }
                unsigned pm = __ballot_sync(0xFFFFFFFFu, (st >> 32) == 2u);
                if (pm) {
                    int lead = 31 - __clz(pm);
                    long long v = (lane >= lead) ? (long long)(unsigned)st : 0;
#pragma unroll
                    for (int o = 16; o > 0; o >>= 1) v += __shfl_xor_sync(0xFFFFFFFFu, v, o);
                    run += v;
                    break;
                } else {
                    long long v = (long long)(unsigned)st;
#pragma unroll
                    for (int o = 16; o > 0; o >>= 1) v += __shfl_xor_sync(0xFFFFFFFFu, v, o);
                    run += v;
                    wbase -= 32;
                }
            }
            if (lane == 0) {
                s_prefix = (int)run;
                d_bstate[bid] = (2ULL << 32) | (unsigned)(run + total);
            }
        }
    }
    __syncthreads();

    if (i < n) {
        int off = s_prefix + incl - pdeg;
        d_off[i] = off;
        d_dinv[i] = rsqrtf((float)deg + 1.0f);
        for (int k = deg; k < pdeg; k++) d_csr[off + k] = NN;  // pads -> zero row
    }
}

// ---------------------------------------------------------------- GEMM (tensor core) + fused CSR fill
// u = (h @ W) * dinv -> fp16. Blocks [0,gemm_blocks): 64 rows x 64 cols, 4 warps
// (small tiles -> whole grid fits in one wave at 12 blocks/SM).
// Blocks >= gemm_blocks: CSR fill (layer 0 only), 2 edges/thread.
__global__ void __launch_bounds__(128) k_gemm(int layer,
                                              const int* __restrict__ x,
                                              const float* __restrict__ emb,
                                              const int* __restrict__ rowi,
                                              const int* __restrict__ coli,
                                              int e_cnt, int gemm_blocks, int n) {
    __shared__ __half sA[64 * 72];    // h rows fp16; reused for D staging
    __shared__ __half sB[64 * 72];    // W [k][n] fp16

    int tid = threadIdx.x;

    if (blockIdx.x >= gemm_blocks) {   // CSR fill blocks
        int e = (blockIdx.x - gemm_blocks) * 256 + tid;
        if (e < e_cnt)
            d_csr[__ldg(&d_off[coli[e]]) + (int)d_epos[e]] = rowi[e];
        e += 128;
        if (e < e_cnt)
            d_csr[__ldg(&d_off[coli[e]]) + (int)d_epos[e]] = rowi[e];
        return;
    }

    int row0 = blockIdx.x * 64;
    const __half* Wh = d_wh + layer * HH * HH;

    // W fp16 -> smem via cp.async (512 16B-chunks)
#pragma unroll
    for (int i = 0; i < 4; i++) {
        int idx = tid + 128 * i;
        int k = idx >> 3, c8 = idx & 7;
        cp16(&sB[k * 72 + c8 * 8], &Wh[k * 64 + c8 * 8]);
    }

    if (layer == 0) {
        const float4* emb4 = (const float4*)emb;
#pragma unroll
        for (int i = 0; i < 8; i++) {
            int idx = tid + 128 * i;
            int r = idx >> 4, c4 = idx & 15;
            int grow = row0 + r;
            float4 v = make_float4(0.f, 0.f, 0.f, 0.f);
            if (grow < n) {
                int vx = __ldg(&x[grow]);
                v = __ldg(&emb4[vx * 16 + c4]);
            }
            __half2* dst = (__half2*)&sA[r * 72 + c4 * 4];
            dst[0] = __float22half2_rn(make_float2(v.x, v.y));
            dst[1] = __float22half2_rn(make_float2(v.z, v.w));
        }
    } else {
#pragma unroll
        for (int i = 0; i < 4; i++) {
            int idx = tid + 128 * i;
            int r = idx >> 3, c8 = idx & 7;
            int grow = row0 + r;
            if (grow < n) cp16(&sA[r * 72 + c8 * 8], &d_hh[grow * 8 + c8]);
            else          *(uint4*)&sA[r * 72 + c8 * 8] = make_uint4(0, 0, 0, 0);
        }
    }
    cp_wait_all();
    __syncthreads();

    int w = tid >> 5, lane = tid & 31;
    int m0 = w * 16;
    int sub = lane >> 3, lrow = lane & 7;
    int bl = lane & 15;

    unsigned af[4][4];
#pragma unroll
    for (int kk = 0; kk < 4; kk++) {
        unsigned aaddr = smem_u32(&sA[(m0 + (sub & 1) * 8 + lrow) * 72 + kk * 16 + (sub >> 1) * 8]);
        asm volatile("ldmatrix.sync.aligned.m8n8.x4.shared.b16 {%0,%1,%2,%3}, [%4];"
                     : "=r"(af[kk][0]), "=r"(af[kk][1]), "=r"(af[kk][2]), "=r"(af[kk][3])
                     : "r"(aaddr));
    }

    float acc[8][4];
#pragma unroll
    for (int j = 0; j < 8; j++) {
        acc[j][0] = 0.f; acc[j][1] = 0.f; acc[j][2] = 0.f; acc[j][3] = 0.f;
    }

#pragma unroll
    for (int kk = 0; kk < 4; kk++) {
#pragma unroll
        for (int j = 0; j < 8; j++) {
            unsigned baddr = smem_u32(&sB[(kk * 16 + (bl >> 3) * 8 + (bl & 7)) * 72 + j * 8]);
            unsigned b0, b1;
            asm volatile("ldmatrix.sync.aligned.m8n8.x2.trans.shared.b16 {%0,%1}, [%2];"
                         : "=r"(b0), "=r"(b1) : "r"(baddr));
            asm volatile("mma.sync.aligned.m16n8k16.row.col.f32.f16.f16.f32 "
                         "{%0,%1,%2,%3},{%4,%5,%6,%7},{%8,%9},{%0,%1,%2,%3};"
                         : "+f"(acc[j][0]), "+f"(acc[j][1]), "+f"(acc[j][2]), "+f"(acc[j][3])
                         : "r"(af[kk][0]), "r"(af[kk][1]), "r"(af[kk][2]), "r"(af[kk][3]),
                           "r"(b0), "r"(b1));
        }
    }
    __syncthreads();   // done reading sA -> reuse for D staging

    int rloc = m0 + (lane >> 2);
    int rA = row0 + rloc, rB = rA + 8;
    float dvA = (rA < n) ? __ldg(&d_dinv[rA]) : 0.f;
    float dvB = (rB < n) ? __ldg(&d_dinv[rB]) : 0.f;
    __half2* sA2 = (__half2*)sA;   // 36 half2 per row
    int ch = lane & 3;
#pragma unroll
    for (int j = 0; j < 8; j++) {
        int c2 = j * 4 + ch;
        sA2[rloc * 36 + c2]       = __float22half2_rn(make_float2(acc[j][0] * dvA, acc[j][1] * dvA));
        sA2[(rloc + 8) * 36 + c2] = __float22half2_rn(make_float2(acc[j][2] * dvB, acc[j][3] * dvB));
    }
    __syncthreads();

#pragma unroll
    for (int i = 0; i < 4; i++) {
        int idx = tid + 128 * i;
        int r = idx >> 3, c8 = idx & 7;
        int grow = row0 + r;
        if (grow < n) d_uh[grow * 8 + c8] = *(uint4*)&sA[r * 72 + c8 * 8];
    }
}

// ---------------------------------------------------------------- gather + epilogue (branch-free)
__global__ void __launch_bounds__(256) k_gather(const float* __restrict__ b, int layer, int n) {
    int idx = blockIdx.x * blockDim.x + threadIdx.x;
    int nd = idx >> 3;
    if (nd >= n) return;
    int p = idx & 7;
    int lane = threadIdx.x & 31;
    unsigned grpmask = 0xFFu << (lane & ~7);

    int beg = __ldg(&d_off[nd]);
    int deg = __ldg(&d_degi[nd]);

    float a0 = 0.f, a1 = 0.f, a2 = 0.f, a3 = 0.f,
          a4 = 0.f, a5 = 0.f, a6 = 0.f, a7 = 0.f;

#define ACC8(v) do {                                                  \
        float2 f;                                                     \
        f = __half22float2(*(__half2*)&(v).x); a0 += f.x; a1 += f.y;  \
        f = __half22float2(*(__half2*)&(v).y); a2 += f.x; a3 += f.y;  \
        f = __half22float2(*(__half2*)&(v).z); a4 += f.x; a5 += f.y;  \
        f = __half22float2(*(__half2*)&(v).w); a6 += f.x; a7 += f.y;  \
    } while (0)

    uint4 vs = d_uh[nd * 8 + p];  // self-loop term
    ACC8(vs);

    for (int k = 0; k < deg; k += 8) {
        int si = __ldg(&d_csr[beg + k + p]);   // pads point at zero row NN
#pragma unroll
        for (int j = 0; j < 8; j++) {
            int s = __shfl_sync(grpmask, si, j, 8);
            uint4 v = __ldg(&d_uh[s * 8 + p]);
            ACC8(v);
        }
    }
#undef ACC8

    float dv = __ldg(&d_dinv[nd]);
    const float4* b4 = (const float4*)b;
    float4 bb0 = __ldg(&b4[p * 2 + 0]);
    float4 bb1 = __ldg(&b4[p * 2 + 1]);

    float v0 = fmaxf(fmaf(dv, a0, bb0.x), 0.f);
    float v1 = fmaxf(fmaf(dv, a1, bb0.y), 0.f);
    float v2 = fmaxf(fmaf(dv, a2, bb0.z), 0.f);
    float v3 = fmaxf(fmaf(dv, a3, bb0.w), 0.f);
    float v4 = fmaxf(fmaf(dv, a4, bb1.x), 0.f);
    float v5 = fmaxf(fmaf(dv, a5, bb1.y), 0.f);
    float v6 = fmaxf(fmaf(dv, a6, bb1.z), 0.f);
    float v7 = fmaxf(fmaf(dv, a7, bb1.w), 0.f);

    if (layer != 0) {
        uint4 hv = d_hh[nd * 8 + p];
        float2 f;
        f = __half22float2(*(__half2*)&hv.x); v0 += f.x; v1 += f.y;
        f = __half22float2(*(__half2*)&hv.y); v2 += f.x; v3 += f.y;
        f = __half22float2(*(__half2*)&hv.z); v4 += f.x; v5 += f.y;
        f = __half22float2(*(__half2*)&hv.w); v6 += f.x; v7 += f.y;
    }

    uint4 o;
    __half2 t0, t1;
    t0 = __float22half2_rn(make_float2(v0, v1));
    t1 = __float22half2_rn(make_float2(v2, v3));
    o.x = *(unsigned*)&t0; o.y = *(unsigned*)&t1;
    t0 = __float22half2_rn(make_float2(v4, v5));
    t1 = __float22half2_rn(make_float2(v6, v7));
    o.z = *(unsigned*)&t0; o.w = *(unsigned*)&t1;
    d_hh[nd * 8 + p] = o;
}

// ---------------------------------------------------------------- fused pool + MLP (+ state cleanup)
__global__ void __launch_bounds__(256) k_poolmlp(const int* __restrict__ batch,
                                                 const float* __restrict__ w1, const float* __restrict__ b1,
                                                 const float* __restrict__ w2, const float* __restrict__ b2,
                                                 const float* __restrict__ w3, const float* __restrict__ b3,
                                                 float* __restrict__ out, int n) {
    __shared__ float sg[8][64];
    __shared__ float sa[8][32];

    int gt = blockIdx.x * blockDim.x + threadIdx.x;
    for (int i = gt; i < n; i += gridDim.x * blockDim.x) d_degi[i] = 0;

    int wlocal = threadIdx.x >> 5;
    int g = gt >> 5;
    int lane = threadIdx.x & 31;
    if (g >= GG) return;

    int lo = 0, hi = n;
    while (lo < hi) { int m = (lo + hi) >> 1; if (__ldg(&batch[m]) < g) lo = m + 1; else hi = m; }
    int lo2 = lo, hi2 = n;
    while (lo2 < hi2) { int m = (lo2 + hi2) >> 1; if (__ldg(&batch[m]) < g + 1) lo2 = m + 1; else hi2 = m; }
    int cnt = lo2 - lo;

    const unsigned* h2 = (const unsigned*)d_hh;
    float s0 = 0.f, s1 = 0.f;
    for (int i = lo; i < lo2; i++) {
        unsigned hv = __ldg(&h2[i * 32 + lane]);
        float2 f = __half22float2(*(__half2*)&hv);
        s0 += f.x; s1 += f.y;
    }
    float inv = 1.0f / fmaxf((float)cnt, 1.0f);
    sg[wlocal][lane * 2 + 0] = s0 * inv;
    sg[wlocal][lane * 2 + 1] = s1 * inv;
    __syncwarp();

    float acc1 = __ldg(&b1[lane]);
#pragma unroll 16
    for (int k = 0; k < 64; k++)
        acc1 = fmaf(sg[wlocal][k], __ldg(&w1[k * 32 + lane]), acc1);
    acc1 = fmaxf(acc1, 0.f);
    sa[wlocal][lane] = acc1;
    __syncwarp();

    float acc2 = 0.f;
    if (lane < 16) {
        acc2 = __ldg(&b2[lane]);
#pragma unroll
        for (int k = 0; k < 32; k++)
            acc2 = fmaf(sa[wlocal][k], __ldg(&w2[k * 16 + lane]), acc2);
        acc2 = fmaxf(acc2, 0.f);
        acc2 *= __ldg(&w3[lane]);
    }
#pragma unroll
    for (int o = 16; o > 0; o >>= 1) acc2 += __shfl_xor_sync(0xFFFFFFFFu, acc2, o);
    if (lane == 0) out[g] = acc2 + __ldg(&b3[0]);
}

// ---------------------------------------------------------------- launch
extern "C" void kernel_launch(void* const* d_in, const int* in_sizes, int n_in,
                              void* d_out, int out_size) {
    const int*   x      = (const int*)d_in[0];
    const int*   ei     = (const int*)d_in[1];
    const int*   batch  = (const int*)d_in[2];
    const float* emb    = (const float*)d_in[3];
    const float* conv_w = (const float*)d_in[4];
    const float* conv_b = (const float*)d_in[5];
    const float* w1     = (const float*)d_in[6];
    const float* b1     = (const float*)d_in[7];
    const float* w2     = (const float*)d_in[8];
    const float* b2     = (const float*)d_in[9];
    const float* w3     = (const float*)d_in[10];
    const float* b3     = (const float*)d_in[11];
    float* out = (float*)d_out;

    int n = in_sizes[0];       // 100000
    int e = in_sizes[1] / 2;   // 3200000
    const int* row = ei;       // source
    const int* col = ei + e;   // target

    int tb = 256;
    int g_n8 = (n * 8 + tb - 1) / tb;
    int g_e  = (e + tb - 1) / tb;
    int g_rows = (n + 63) / 64;                  // 64-row GEMM tiles
    int fill_blocks = (e + 255) / 256;           // 2 edges/thread @128 threads
    int nb_scan = (n + SCAN_BS - 1) / SCAN_BS;
    int wcvt_blocks = (3 * HH * HH / 2 + tb - 1) / tb;   // 24

    k_deg<<<g_e + wcvt_blocks, tb>>>(col, conv_w, e, g_e);
    k_scan<<<nb_scan, SCAN_BS>>>(n);
    // layer-0 GEMM fused with CSR fill (independent, overlapped)
    k_gemm<<<g_rows + fill_blocks, 128>>>(0, x, emb, row, col, e, g_rows, n);
    k_gather<<<g_n8, tb>>>(conv_b, 0, n);
    for (int l = 1; l < 3; l++) {
        k_gemm<<<g_rows, 128>>>(l, x, emb, row, col, 0, g_rows, n);
        k_gather<<<g_n8, tb>>>(conv_b + l * HH, l, n);
    }
    k_poolmlp<<<(GG * 32 + tb - 1) / tb, tb>>>(batch, w1, b1, w2, b2, w3, b3, out, n);
}